// round 13
// baseline (speedup 1.0000x reference)
#include <cuda_runtime.h>
#include <cuda.h>
#include <cuda_fp16.h>
#include <cstdint>
#include <cstddef>
#include <math.h>

#define DIM   768
#define BATCH 8
#define SEQ   2048
#define QKVD  (3 * DIM)

// ------- scratch (static device globals; 1024B-aligned for TMA) -------------
__device__ __align__(1024) __half g_xh[(size_t)BATCH * SEQ * DIM];
__device__ __align__(1024) __half g_wqkvh[(size_t)QKVD * DIM];
__device__ __align__(1024) __half g_wprojh[(size_t)DIM * DIM];
__device__ __align__(1024) __half g_qkvh[(size_t)BATCH * SEQ * QKVD];
__device__ __align__(1024) __half g_e[(size_t)BATCH * SEQ * SEQ];
__device__ __align__(1024) float  g_sum[(size_t)BATCH * SEQ];
__device__ __align__(1024) __half g_vth[(size_t)BATCH * DIM * SEQ];
__device__ __align__(1024) __half g_aoh[(size_t)BATCH * SEQ * DIM];

// ---------------- PTX helpers ----------------------------------------------
__device__ __forceinline__ uint32_t smem_u32(const void* p) {
    uint32_t a;
    asm("{ .reg .u64 t; cvta.to.shared.u64 t, %1; cvt.u32.u64 %0, t; }"
        : "=r"(a) : "l"(p));
    return a;
}
__device__ __forceinline__ void mma_f16(float* d, const uint32_t* a, const uint32_t* b) {
    asm volatile(
        "mma.sync.aligned.m16n8k16.row.col.f32.f16.f16.f32 "
        "{%0,%1,%2,%3}, {%4,%5,%6,%7}, {%8,%9}, {%0,%1,%2,%3};"
        : "+f"(d[0]), "+f"(d[1]), "+f"(d[2]), "+f"(d[3])
        : "r"(a[0]), "r"(a[1]), "r"(a[2]), "r"(a[3]), "r"(b[0]), "r"(b[1]));
}
__device__ __forceinline__ void ldsm_x4(uint32_t& r0, uint32_t& r1,
                                        uint32_t& r2, uint32_t& r3, uint32_t addr) {
    asm volatile("ldmatrix.sync.aligned.m8n8.x4.shared.b16 {%0,%1,%2,%3}, [%4];"
                 : "=r"(r0), "=r"(r1), "=r"(r2), "=r"(r3) : "r"(addr));
}
__device__ __forceinline__ void mbar_init(uint32_t mbar, uint32_t cnt) {
    asm volatile("mbarrier.init.shared.b64 [%0], %1;" :: "r"(mbar), "r"(cnt) : "memory");
}
__device__ __forceinline__ void mbar_expect_tx(uint32_t mbar, uint32_t bytes) {
    asm volatile("mbarrier.arrive.expect_tx.shared.b64 _, [%0], %1;"
                 :: "r"(mbar), "r"(bytes) : "memory");
}
__device__ __forceinline__ void mbar_arrive(uint32_t mbar) {
    asm volatile("mbarrier.arrive.shared.b64 _, [%0];" :: "r"(mbar) : "memory");
}
__device__ __forceinline__ void mbar_wait(uint32_t mbar, uint32_t parity) {
    asm volatile(
        "{\n\t.reg .pred P;\n\t"
        "WLP_%=:\n\t"
        "mbarrier.try_wait.parity.acquire.cta.shared::cta.b64 P, [%0], %1, 0x989680;\n\t"
        "@P bra.uni WDN_%=;\n\t"
        "bra.uni WLP_%=;\n\t"
        "WDN_%=:\n\t}"
        :: "r"(mbar), "r"(parity) : "memory");
}
__device__ __forceinline__ void tma_load3d(uint32_t dst, const CUtensorMap* map,
                                           int x, int y, int z, uint32_t mbar) {
    asm volatile(
        "cp.async.bulk.tensor.3d.shared::cta.global.tile.mbarrier::complete_tx::bytes "
        "[%0], [%1, {%2, %3, %4}], [%5];"
        :: "r"(dst), "l"(map), "r"(x), "r"(y), "r"(z), "r"(mbar) : "memory");
}

// ---------------- GEMM config ----------------------------------------------
// C[M,N] = f(alpha * A[M,K] @ B[N,K]^T). fp16 via TMA, accum fp32.
// 128x64x64 tiles, 256 thr (8 warps, 4x2, warp tile 32x32),
// 3-stage TMA+mbarrier ring, <=85 regs -> 3 CTAs/SM (24 warps).
// MODE 0: +bias fp16 | 1: exp + rowsum fp16 | 2: /sums[row] fp16 | 3: +bias fp32
constexpr int BM = 128, BN = 64, BK = 64, NSTAGE = 3;
constexpr int A_TILE_B  = BM * 128;                       // 16384
constexpr int B_TILE_B  = BN * 128;                       // 8192
constexpr int STAGE_BYTES = A_TILE_B + B_TILE_B;          // 24576
constexpr int SMEM_DYN  = NSTAGE * STAGE_BYTES + 1024;    // 74752

template <int MODE>
__global__ __launch_bounds__(256, 3)
void gemm_tma(const __grid_constant__ CUtensorMap mapA,
              const __grid_constant__ CUtensorMap mapB,
              int kOffA, int kOffB,
              const float* __restrict__ aux, float* __restrict__ sums,
              void* __restrict__ Cv,
              int K, int ldc, size_t sC, size_t sAux, float alpha)
{
    extern __shared__ char smem_raw[];
    __shared__ __align__(8) uint64_t s_full[NSTAGE];
    __shared__ __align__(8) uint64_t s_empty[NSTAGE];
    const uint32_t smem0 = (smem_u32(smem_raw) + 1023u) & ~1023u;

    const int tid  = threadIdx.x;
    const int wid  = tid >> 5;
    const int lane = tid & 31;
    const int g    = lane >> 2;
    const int tig  = lane & 3;
    const int wm0  = (wid & 3) * 32;   // warp m offset (4 warps)
    const int wn0  = (wid >> 2) * 32;  // warp n offset (2 warps)

    const int brow = blockIdx.y * BM;
    const int bcol = blockIdx.x * BN;
    const int bz   = blockIdx.z;

    const int iters = K / BK;

    if (tid == 0) {
#pragma unroll
        for (int s = 0; s < NSTAGE; s++) {
            mbar_init(smem_u32(&s_full[s]), 1);
            mbar_init(smem_u32(&s_empty[s]), 8);   // one arrive per warp
        }
        asm volatile("fence.proxy.async.shared::cta;" ::: "memory");
    }
    __syncthreads();

    if (tid == 0) {
#pragma unroll
        for (int s = 0; s < NSTAGE; s++) {
            const uint32_t sa = smem0 + s * STAGE_BYTES;
            mbar_expect_tx(smem_u32(&s_full[s]), STAGE_BYTES);
            tma_load3d(sa, &mapA, s * BK + kOffA, brow, bz, smem_u32(&s_full[s]));
            tma_load3d(sa + A_TILE_B, &mapB, s * BK + kOffB, bcol, bz,
                       smem_u32(&s_full[s]));
        }
    }

    const uint32_t hi = (uint32_t)(lane >> 4);
    uint32_t aoff[2], axr[2], boff[2], bxr[2];
#pragma unroll
    for (int mi = 0; mi < 2; mi++) {
        int row = wm0 + mi * 16 + (lane & 15);
        aoff[mi] = (uint32_t)(row * 128);
        axr[mi]  = (uint32_t)(row & 7);
    }
#pragma unroll
    for (int p = 0; p < 2; p++) {
        int row = wn0 + p * 16 + (lane & 15);
        boff[p] = (uint32_t)(row * 128);
        bxr[p]  = (uint32_t)(row & 7);
    }

    float acc[2][4][4];
#pragma unroll
    for (int mi = 0; mi < 2; mi++)
#pragma unroll
        for (int ni = 0; ni < 4; ni++)
#pragma unroll
            for (int r = 0; r < 4; r++) acc[mi][ni][r] = 0.0f;

    for (int it = 0; it < iters; it++) {
        const int s = it % NSTAGE;
        const uint32_t u = (uint32_t)(it / NSTAGE) & 1u;
        mbar_wait(smem_u32(&s_full[s]), u);

        const uint32_t sa = smem0 + s * STAGE_BYTES;
        const uint32_t sb = sa + A_TILE_B;

#pragma unroll
        for (int ks = 0; ks < 4; ks++) {
            const uint32_t ch = 2 * ks + hi;
            uint32_t af[2][4], bf[4][2];
#pragma unroll
            for (int mi = 0; mi < 2; mi++)
                ldsm_x4(af[mi][0], af[mi][1], af[mi][2], af[mi][3],
                        sa + aoff[mi] + ((ch ^ axr[mi]) << 4));
#pragma unroll
            for (int p = 0; p < 2; p++)
                ldsm_x4(bf[2 * p][0], bf[2 * p + 1][0], bf[2 * p][1], bf[2 * p + 1][1],
                        sb + boff[p] + ((ch ^ bxr[p]) << 4));
#pragma unroll
            for (int mi = 0; mi < 2; mi++)
#pragma unroll
                for (int ni = 0; ni < 4; ni++)
                    mma_f16(acc[mi][ni], af[mi], bf[ni]);
        }

        if (lane == 0) mbar_arrive(smem_u32(&s_empty[s]));
        if (tid == 0 && it + NSTAGE < iters) {
            mbar_wait(smem_u32(&s_empty[s]), u);
            mbar_expect_tx(smem_u32(&s_full[s]), STAGE_BYTES);
            tma_load3d(sa, &mapA, (it + NSTAGE) * BK + kOffA, brow, bz,
                       smem_u32(&s_full[s]));
            tma_load3d(sb, &mapB, (it + NSTAGE) * BK + kOffB, bcol, bz,
                       smem_u32(&s_full[s]));
        }
    }

    // ---- epilogue ----
    float2 bv[4];
    if (MODE == 0 || MODE == 3) {
#pragma unroll
        for (int ni = 0; ni < 4; ni++)
            bv[ni] = *reinterpret_cast<const float2*>(&aux[bcol + wn0 + ni * 8 + 2 * tig]);
    }
    float rs[2][2];
    if (MODE == 2) {
        const float* sm = aux + (size_t)bz * sAux;
#pragma unroll
        for (int mi = 0; mi < 2; mi++) {
            const int r0 = brow + wm0 + mi * 16 + g;
            rs[mi][0] = 1.0f / sm[r0];
            rs[mi][1] = 1.0f / sm[r0 + 8];
        }
    }
    float rowacc[2][2];
    if (MODE == 1) {
        rowacc[0][0] = rowacc[0][1] = rowacc[1][0] = rowacc[1][1] = 0.0f;
    }
#pragma unroll
    for (int mi = 0; mi < 2; mi++) {
        const int r0 = brow + wm0 + mi * 16 + g;
#pragma unroll
        for (int ni = 0; ni < 4; ni++) {
            const int c = bcol + wn0 + ni * 8 + 2 * tig;
            float2 v0, v1;
            v0.x = acc[mi][ni][0] * alpha;
            v0.y = acc[mi][ni][1] * alpha;
            v1.x = acc[mi][ni][2] * alpha;
            v1.y = acc[mi][ni][3] * alpha;
            if (MODE == 0 || MODE == 3) {
                v0.x += bv[ni].x; v0.y += bv[ni].y;
                v1.x += bv[ni].x; v1.y += bv[ni].y;
            }
            if (MODE == 1) {
                v0.x = __expf(v0.x); v0.y = __expf(v0.y);
                v1.x = __expf(v1.x); v1.y = __expf(v1.y);
                rowacc[mi][0] += v0.x + v0.y;
                rowacc[mi][1] += v1.x + v1.y;
            }
            if (MODE == 2) {
                v0.x *= rs[mi][0]; v0.y *= rs[mi][0];
                v1.x *= rs[mi][1]; v1.y *= rs[mi][1];
            }
            if (MODE == 3) {
                float* C = (float*)Cv + (size_t)bz * sC;
                *reinterpret_cast<float2*>(&C[(size_t)r0 * ldc + c]) = v0;
                *reinterpret_cast<float2*>(&C[(size_t)(r0 + 8) * ldc + c]) = v1;
            } else {
                __half* C = (__half*)Cv + (size_t)bz * sC;
                *reinterpret_cast<__half2*>(&C[(size_t)r0 * ldc + c]) =
                    __floats2half2_rn(v0.x, v0.y);
                *reinterpret_cast<__half2*>(&C[(size_t)(r0 + 8) * ldc + c]) =
                    __floats2half2_rn(v1.x, v1.y);
            }
        }
    }
    if (MODE == 1) {
#pragma unroll
        for (int mi = 0; mi < 2; mi++) {
#pragma unroll
            for (int h = 0; h < 2; h++) {
                float v = rowacc[mi][h];
                v += __shfl_xor_sync(0xffffffffu, v, 1);
                v += __shfl_xor_sync(0xffffffffu, v, 2);
                if (tig == 0) {
                    const int r0 = brow + wm0 + mi * 16 + g + h * 8;
                    atomicAdd(&sums[(size_t)bz * SEQ + r0], v);
                }
            }
        }
    }
}

// ---------------- fp32 -> fp16 conversion ----------------------------------
__global__ __launch_bounds__(256) void cvt_half_kernel(const float4* __restrict__ in,
                                                       __half2* __restrict__ out, int n4)
{
    int i = blockIdx.x * blockDim.x + threadIdx.x;
    if (i < n4) {
        float4 v = in[i];
        out[2 * i]     = __floats2half2_rn(v.x, v.y);
        out[2 * i + 1] = __floats2half2_rn(v.z, v.w);
    }
}

// ---------------- V transpose: qkvh[b,n,2*DIM+d] -> vth[b,d,n] -------------
__global__ __launch_bounds__(256) void transpose_v(const __half* __restrict__ qkv,
                                                   __half* __restrict__ vt)
{
    __shared__ __half t[32][34];
    const int b = blockIdx.z;
    const int n0 = blockIdx.x * 32, d0 = blockIdx.y * 32;
    const int tx = threadIdx.x, ty = threadIdx.y;   // 32 x 8
#pragma unroll
    for (int j = 0; j < 32; j += 8)
        t[ty + j][tx] = qkv[(size_t)b * SEQ * QKVD + (size_t)(n0 + ty + j) * QKVD
                            + 2 * DIM + d0 + tx];
    __syncthreads();
#pragma unroll
    for (int j = 0; j < 32; j += 8)
        vt[(size_t)b * DIM * SEQ + (size_t)(d0 + ty + j) * SEQ + n0 + tx] = t[tx][ty + j];
}

// ---------------- host-side tensormap setup --------------------------------
typedef CUresult (*PFN_encodeTiled)(
    CUtensorMap*, CUtensorMapDataType, cuuint32_t, void*,
    const cuuint64_t*, const cuuint64_t*, const cuuint32_t*, const cuuint32_t*,
    CUtensorMapInterleave, CUtensorMapSwizzle, CUtensorMapL2promotion,
    CUtensorMapFloatOOBfill);

static void make_map(PFN_encodeTiled enc, CUtensorMap* m, void* p,
                     uint64_t inner, uint64_t rows, uint64_t batch, uint32_t boxRows)
{
    cuuint64_t dims[3]    = {inner, rows, batch};
    cuuint64_t strides[2] = {inner * 2, inner * rows * 2};
    cuuint32_t box[3]     = {64, boxRows, 1};
    cuuint32_t es[3]      = {1, 1, 1};
    enc(m, CU_TENSOR_MAP_DATA_TYPE_FLOAT16, 3, p, dims, strides, box, es,
        CU_TENSOR_MAP_INTERLEAVE_NONE, CU_TENSOR_MAP_SWIZZLE_128B,
        CU_TENSOR_MAP_L2_PROMOTION_L2_128B, CU_TENSOR_MAP_FLOAT_OOB_FILL_NONE);
}

// ---------------------------------------------------------------------------
extern "C" void kernel_launch(void* const* d_in, const int* in_sizes, int n_in,
                              void* d_out, int out_size)
{
    const float* x      = (const float*)d_in[0];
    const float* w_qkv  = (const float*)d_in[1];
    const float* b_qkv  = (const float*)d_in[2];
    const float* w_proj = (const float*)d_in[3];
    const float* b_proj = (const float*)d_in[4];
    float* out = (float*)d_out;

    static __half *xh = nullptr, *wqkvh = nullptr, *wprojh = nullptr;
    static __half *qkvh = nullptr, *eh = nullptr, *vth = nullptr, *aoh = nullptr;
    static float *sums = nullptr;
    static CUtensorMap mXh, mWqkv, mQkvA, mQkvB, mE, mVt, mAo, mWproj;
    if (!xh) {
        cudaGetSymbolAddress((void**)&xh,     g_xh);
        cudaGetSymbolAddress((void**)&wqkvh,  g_wqkvh);
        cudaGetSymbolAddress((void**)&wprojh, g_wprojh);
        cudaGetSymbolAddress((void**)&qkvh,   g_qkvh);
        cudaGetSymbolAddress((void**)&eh,     g_e);
        cudaGetSymbolAddress((void**)&sums,   g_sum);
        cudaGetSymbolAddress((void**)&vth,    g_vth);
        cudaGetSymbolAddress((void**)&aoh,    g_aoh);
        cudaFuncSetAttribute(gemm_tma<0>, cudaFuncAttributeMaxDynamicSharedMemorySize, SMEM_DYN);
        cudaFuncSetAttribute(gemm_tma<1>, cudaFuncAttributeMaxDynamicSharedMemorySize, SMEM_DYN);
        cudaFuncSetAttribute(gemm_tma<2>, cudaFuncAttributeMaxDynamicSharedMemorySize, SMEM_DYN);
        cudaFuncSetAttribute(gemm_tma<3>, cudaFuncAttributeMaxDynamicSharedMemorySize, SMEM_DYN);

        void* fn = nullptr;
        cudaDriverEntryPointQueryResult qr;
        cudaGetDriverEntryPoint("cuTensorMapEncodeTiled", &fn,
                                cudaEnableDefault, &qr);
        PFN_encodeTiled enc = (PFN_encodeTiled)fn;
        // A-side maps (box 128 rows)
        make_map(enc, &mXh,   xh,   DIM,  (uint64_t)BATCH * SEQ, 1,     128);
        make_map(enc, &mQkvA, qkvh, QKVD, SEQ,                   BATCH, 128);
        make_map(enc, &mE,    eh,   SEQ,  SEQ,                   BATCH, 128);
        make_map(enc, &mAo,   aoh,  DIM,  (uint64_t)BATCH * SEQ, 1,     128);
        // B-side maps (box 64 rows)
        make_map(enc, &mWqkv, wqkvh, DIM,  QKVD,                 1,     64);
        make_map(enc, &mQkvB, qkvh,  QKVD, SEQ,                  BATCH, 64);
        make_map(enc, &mVt,   vth,   SEQ,  DIM,                  BATCH, 64);
        make_map(enc, &mWproj,wprojh,DIM,  DIM,                  1,     64);
    }

    const int M_ALL = BATCH * SEQ;
    const float alpha_s = 1.0f / (sqrtf((float)DIM) * 3.0f);

    // 0) convert operands to fp16; zero rowsums
    {
        int n4 = BATCH * SEQ * DIM / 4;
        cvt_half_kernel<<<(n4 + 255) / 256, 256>>>((const float4*)x, (__half2*)xh, n4);
        n4 = QKVD * DIM / 4;
        cvt_half_kernel<<<(n4 + 255) / 256, 256>>>((const float4*)w_qkv, (__half2*)wqkvh, n4);
        n4 = DIM * DIM / 4;
        cvt_half_kernel<<<(n4 + 255) / 256, 256>>>((const float4*)w_proj, (__half2*)wprojh, n4);
        cudaMemsetAsync(sums, 0, (size_t)BATCH * SEQ * sizeof(float));
    }

    // 1) qkv = x @ w_qkv^T + b_qkv -> fp16
    gemm_tma<0><<<dim3(QKVD / BN, M_ALL / BM, 1), 256, SMEM_DYN>>>(
        mXh, mWqkv, 0, 0, b_qkv, nullptr, qkvh, DIM, QKVD, 0, 0, 1.0f);

    // 1b) Vt[b,d,n] fp16
    transpose_v<<<dim3(SEQ / 32, DIM / 32, BATCH), dim3(32, 8)>>>(qkvh, vth);

    // 2) E[b] = exp(alpha * Q_b @ K_b^T) -> fp16, + atomic rowsums
    gemm_tma<1><<<dim3(SEQ / BN, SEQ / BM, BATCH), 256, SMEM_DYN>>>(
        mQkvA, mQkvB, 0, DIM, nullptr, sums, eh,
        DIM, SEQ, (size_t)SEQ * SEQ, 0, alpha_s);

    // 3) attn_out[b] = (E_b @ Vt_b^T) / sums[row] -> fp16
    gemm_tma<2><<<dim3(DIM / BN, SEQ / BM, BATCH), 256, SMEM_DYN>>>(
        mE, mVt, 0, 0, sums, nullptr, aoh,
        SEQ, DIM, (size_t)SEQ * DIM, SEQ, 1.0f);

    // 4) out = attn_out @ w_proj^T + b_proj -> fp32
    gemm_tma<3><<<dim3(DIM / BN, M_ALL / BM, 1), 256, SMEM_DYN>>>(
        mAo, mWproj, 0, 0, b_proj, nullptr, out, DIM, DIM, 0, 0, 1.0f);
}

// round 14
// speedup vs baseline: 1.0422x; 1.0422x over previous
#include <cuda_runtime.h>
#include <cuda.h>
#include <cuda_fp16.h>
#include <cstdint>
#include <cstddef>
#include <math.h>

#define DIM   768
#define BATCH 8
#define SEQ   2048
#define QKVD  (3 * DIM)

// ------- scratch (static device globals; 1024B-aligned for TMA) -------------
__device__ __align__(1024) __half g_xh[(size_t)BATCH * SEQ * DIM];
__device__ __align__(1024) __half g_wqkvh[(size_t)QKVD * DIM];
__device__ __align__(1024) __half g_wprojh[(size_t)DIM * DIM];
__device__ __align__(1024) __half g_qkvh[(size_t)BATCH * SEQ * QKVD];
__device__ __align__(1024) __half g_e[(size_t)BATCH * SEQ * SEQ];
__device__ __align__(1024) float  g_sum[(size_t)BATCH * SEQ];
__device__ __align__(1024) __half g_vth[(size_t)BATCH * DIM * SEQ];
__device__ __align__(1024) __half g_aoh[(size_t)BATCH * SEQ * DIM];

// ---------------- PTX helpers ----------------------------------------------
__device__ __forceinline__ uint32_t smem_u32(const void* p) {
    uint32_t a;
    asm("{ .reg .u64 t; cvta.to.shared.u64 t, %1; cvt.u32.u64 %0, t; }"
        : "=r"(a) : "l"(p));
    return a;
}
__device__ __forceinline__ void mma_f16(float* d, const uint32_t* a, const uint32_t* b) {
    asm volatile(
        "mma.sync.aligned.m16n8k16.row.col.f32.f16.f16.f32 "
        "{%0,%1,%2,%3}, {%4,%5,%6,%7}, {%8,%9}, {%0,%1,%2,%3};"
        : "+f"(d[0]), "+f"(d[1]), "+f"(d[2]), "+f"(d[3])
        : "r"(a[0]), "r"(a[1]), "r"(a[2]), "r"(a[3]), "r"(b[0]), "r"(b[1]));
}
__device__ __forceinline__ void ldsm_x4(uint32_t& r0, uint32_t& r1,
                                        uint32_t& r2, uint32_t& r3, uint32_t addr) {
    asm volatile("ldmatrix.sync.aligned.m8n8.x4.shared.b16 {%0,%1,%2,%3}, [%4];"
                 : "=r"(r0), "=r"(r1), "=r"(r2), "=r"(r3) : "r"(addr));
}
__device__ __forceinline__ void mbar_init(uint32_t mbar, uint32_t cnt) {
    asm volatile("mbarrier.init.shared.b64 [%0], %1;" :: "r"(mbar), "r"(cnt) : "memory");
}
__device__ __forceinline__ void mbar_expect_tx(uint32_t mbar, uint32_t bytes) {
    asm volatile("mbarrier.arrive.expect_tx.shared.b64 _, [%0], %1;"
                 :: "r"(mbar), "r"(bytes) : "memory");
}
__device__ __forceinline__ void mbar_arrive(uint32_t mbar) {
    asm volatile("mbarrier.arrive.shared.b64 _, [%0];" :: "r"(mbar) : "memory");
}
__device__ __forceinline__ void mbar_wait(uint32_t mbar, uint32_t parity) {
    asm volatile(
        "{\n\t.reg .pred P;\n\t"
        "WLP_%=:\n\t"
        "mbarrier.try_wait.parity.acquire.cta.shared::cta.b64 P, [%0], %1, 0x989680;\n\t"
        "@P bra.uni WDN_%=;\n\t"
        "bra.uni WLP_%=;\n\t"
        "WDN_%=:\n\t}"
        :: "r"(mbar), "r"(parity) : "memory");
}
__device__ __forceinline__ void tma_load3d(uint32_t dst, const CUtensorMap* map,
                                           int x, int y, int z, uint32_t mbar) {
    asm volatile(
        "cp.async.bulk.tensor.3d.shared::cta.global.tile.mbarrier::complete_tx::bytes "
        "[%0], [%1, {%2, %3, %4}], [%5];"
        :: "r"(dst), "l"(map), "r"(x), "r"(y), "r"(z), "r"(mbar) : "memory");
}

// ---------------- GEMM config ----------------------------------------------
// C[M,N] = f(alpha * A[M,K] @ B[N,K]^T). fp16 via TMA, accum fp32.
// 128x128x64 tiles, 256 thr (warp tile 32x128-ish: 4x2 warps),
// 3-stage TMA+mbarrier ring, stage-unrolled mainloop, 2 CTAs/SM.
// MODE 0: +bias fp16 | 1: exp + rowsum fp16 | 2: /sums[row] fp16 | 3: +bias fp32
constexpr int BM = 128, BN = 128, BK = 64, NSTAGE = 3;
constexpr int TILE_BYTES  = BM * 128;                   // 16384
constexpr int STAGE_BYTES = 2 * TILE_BYTES;             // 32768
constexpr int SMEM_DYN    = NSTAGE * STAGE_BYTES + 1024;

template <int MODE>
__global__ __launch_bounds__(256, 2)
void gemm_tma(const __grid_constant__ CUtensorMap mapA,
              const __grid_constant__ CUtensorMap mapB,
              int kOffA, int kOffB,
              const float* __restrict__ aux, float* __restrict__ sums,
              void* __restrict__ Cv,
              int K, int ldc, size_t sC, size_t sAux, float alpha)
{
    extern __shared__ char smem_raw[];
    __shared__ __align__(8) uint64_t s_full[NSTAGE];
    __shared__ __align__(8) uint64_t s_empty[NSTAGE];
    const uint32_t smem0 = (smem_u32(smem_raw) + 1023u) & ~1023u;

    const int tid  = threadIdx.x;
    const int wid  = tid >> 5;
    const int lane = tid & 31;
    const int g    = lane >> 2;
    const int tig  = lane & 3;
    const int wm0  = (wid & 3) * 32;
    const int wn0  = (wid >> 2) * 64;

    const int brow = blockIdx.y * BM;
    const int bcol = blockIdx.x * BN;
    const int bz   = blockIdx.z;

    const int iters = K / BK;

    if (tid == 0) {
#pragma unroll
        for (int s = 0; s < NSTAGE; s++) {
            mbar_init(smem_u32(&s_full[s]), 1);
            mbar_init(smem_u32(&s_empty[s]), 8);   // one arrive per warp
        }
        asm volatile("fence.proxy.async.shared::cta;" ::: "memory");
    }
    __syncthreads();

    if (tid == 0) {
#pragma unroll
        for (int s = 0; s < NSTAGE; s++) {
            const uint32_t sa = smem0 + s * STAGE_BYTES;
            mbar_expect_tx(smem_u32(&s_full[s]), STAGE_BYTES);
            tma_load3d(sa, &mapA, s * BK + kOffA, brow, bz, smem_u32(&s_full[s]));
            tma_load3d(sa + TILE_BYTES, &mapB, s * BK + kOffB, bcol, bz,
                       smem_u32(&s_full[s]));
        }
    }

    const uint32_t hi = (uint32_t)(lane >> 4);
    uint32_t aoff[2], axr[2], boff[4], bxr[4];
#pragma unroll
    for (int mi = 0; mi < 2; mi++) {
        int row = wm0 + mi * 16 + (lane & 15);
        aoff[mi] = (uint32_t)(row * 128);
        axr[mi]  = (uint32_t)(row & 7);
    }
#pragma unroll
    for (int p = 0; p < 4; p++) {
        int row = wn0 + p * 16 + (lane & 15);
        boff[p] = (uint32_t)(row * 128);
        bxr[p]  = (uint32_t)(row & 7);
    }

    float acc[2][8][4];
#pragma unroll
    for (int mi = 0; mi < 2; mi++)
#pragma unroll
        for (int ni = 0; ni < 8; ni++)
#pragma unroll
            for (int r = 0; r < 4; r++) acc[mi][ni][r] = 0.0f;

    // one tile of work on stage s (compile-time), parity u, iteration it
    auto body = [&](int s, uint32_t u, int it) {
        mbar_wait(smem_u32(&s_full[s]), u);
        const uint32_t sa = smem0 + s * STAGE_BYTES;
        const uint32_t sb = sa + TILE_BYTES;
#pragma unroll
        for (int ks = 0; ks < 4; ks++) {
            const uint32_t ch = 2 * ks + hi;
            uint32_t af[2][4], bf[8][2];
#pragma unroll
            for (int mi = 0; mi < 2; mi++)
                ldsm_x4(af[mi][0], af[mi][1], af[mi][2], af[mi][3],
                        sa + aoff[mi] + ((ch ^ axr[mi]) << 4));
#pragma unroll
            for (int p = 0; p < 4; p++)
                ldsm_x4(bf[2 * p][0], bf[2 * p + 1][0], bf[2 * p][1], bf[2 * p + 1][1],
                        sb + boff[p] + ((ch ^ bxr[p]) << 4));
#pragma unroll
            for (int mi = 0; mi < 2; mi++)
#pragma unroll
                for (int ni = 0; ni < 8; ni++)
                    mma_f16(acc[mi][ni], af[mi], bf[ni]);
        }
        if (lane == 0) mbar_arrive(smem_u32(&s_empty[s]));
        if (tid == 0 && it + NSTAGE < iters) {
            mbar_wait(smem_u32(&s_empty[s]), u);
            mbar_expect_tx(smem_u32(&s_full[s]), STAGE_BYTES);
            tma_load3d(sa, &mapA, (it + NSTAGE) * BK + kOffA, brow, bz,
                       smem_u32(&s_full[s]));
            tma_load3d(sb, &mapB, (it + NSTAGE) * BK + kOffB, bcol, bz,
                       smem_u32(&s_full[s]));
        }
    };

    const int nfull = iters / NSTAGE;
    const int nrem  = iters - nfull * NSTAGE;
    int it = 0;
    for (int blk = 0; blk < nfull; blk++) {
        const uint32_t u = (uint32_t)blk & 1u;
#pragma unroll
        for (int s = 0; s < NSTAGE; s++) { body(s, u, it); it++; }
    }
    {
        const uint32_t u = (uint32_t)nfull & 1u;
#pragma unroll
        for (int s = 0; s < NSTAGE - 1; s++) {
            if (s < nrem) { body(s, u, it); it++; }
        }
    }

    // ---- epilogue ----
    float2 bv[8];
    if (MODE == 0 || MODE == 3) {
#pragma unroll
        for (int ni = 0; ni < 8; ni++)
            bv[ni] = *reinterpret_cast<const float2*>(&aux[bcol + wn0 + ni * 8 + 2 * tig]);
    }
    float rs[2][2];
    if (MODE == 2) {
        const float* sm = aux + (size_t)bz * sAux;
#pragma unroll
        for (int mi = 0; mi < 2; mi++) {
            const int r0 = brow + wm0 + mi * 16 + g;
            rs[mi][0] = 1.0f / sm[r0];
            rs[mi][1] = 1.0f / sm[r0 + 8];
        }
    }
    float rowacc[2][2];
    if (MODE == 1) {
        rowacc[0][0] = rowacc[0][1] = rowacc[1][0] = rowacc[1][1] = 0.0f;
    }
#pragma unroll
    for (int mi = 0; mi < 2; mi++) {
        const int r0 = brow + wm0 + mi * 16 + g;
#pragma unroll
        for (int ni = 0; ni < 8; ni++) {
            const int c = bcol + wn0 + ni * 8 + 2 * tig;
            float2 v0, v1;
            v0.x = acc[mi][ni][0] * alpha;
            v0.y = acc[mi][ni][1] * alpha;
            v1.x = acc[mi][ni][2] * alpha;
            v1.y = acc[mi][ni][3] * alpha;
            if (MODE == 0 || MODE == 3) {
                v0.x += bv[ni].x; v0.y += bv[ni].y;
                v1.x += bv[ni].x; v1.y += bv[ni].y;
            }
            if (MODE == 1) {
                v0.x = __expf(v0.x); v0.y = __expf(v0.y);
                v1.x = __expf(v1.x); v1.y = __expf(v1.y);
                rowacc[mi][0] += v0.x + v0.y;
                rowacc[mi][1] += v1.x + v1.y;
            }
            if (MODE == 2) {
                v0.x *= rs[mi][0]; v0.y *= rs[mi][0];
                v1.x *= rs[mi][1]; v1.y *= rs[mi][1];
            }
            if (MODE == 3) {
                float* C = (float*)Cv + (size_t)bz * sC;
                *reinterpret_cast<float2*>(&C[(size_t)r0 * ldc + c]) = v0;
                *reinterpret_cast<float2*>(&C[(size_t)(r0 + 8) * ldc + c]) = v1;
            } else {
                __half* C = (__half*)Cv + (size_t)bz * sC;
                *reinterpret_cast<__half2*>(&C[(size_t)r0 * ldc + c]) =
                    __floats2half2_rn(v0.x, v0.y);
                *reinterpret_cast<__half2*>(&C[(size_t)(r0 + 8) * ldc + c]) =
                    __floats2half2_rn(v1.x, v1.y);
            }
        }
    }
    if (MODE == 1) {
#pragma unroll
        for (int mi = 0; mi < 2; mi++) {
#pragma unroll
            for (int h = 0; h < 2; h++) {
                float v = rowacc[mi][h];
                v += __shfl_xor_sync(0xffffffffu, v, 1);
                v += __shfl_xor_sync(0xffffffffu, v, 2);
                if (tig == 0) {
                    const int r0 = brow + wm0 + mi * 16 + g + h * 8;
                    atomicAdd(&sums[(size_t)bz * SEQ + r0], v);
                }
            }
        }
    }
}

// ---------------- fp32 -> fp16 conversion ----------------------------------
__global__ __launch_bounds__(256) void cvt_half_kernel(const float4* __restrict__ in,
                                                       __half2* __restrict__ out, int n4)
{
    int i = blockIdx.x * blockDim.x + threadIdx.x;
    if (i < n4) {
        float4 v = in[i];
        out[2 * i]     = __floats2half2_rn(v.x, v.y);
        out[2 * i + 1] = __floats2half2_rn(v.z, v.w);
    }
}

// ---------------- V transpose: qkvh[b,n,2*DIM+d] -> vth[b,d,n] -------------
__global__ __launch_bounds__(256) void transpose_v(const __half* __restrict__ qkv,
                                                   __half* __restrict__ vt)
{
    __shared__ __half t[32][34];
    const int b = blockIdx.z;
    const int n0 = blockIdx.x * 32, d0 = blockIdx.y * 32;
    const int tx = threadIdx.x, ty = threadIdx.y;   // 32 x 8
#pragma unroll
    for (int j = 0; j < 32; j += 8)
        t[ty + j][tx] = qkv[(size_t)b * SEQ * QKVD + (size_t)(n0 + ty + j) * QKVD
                            + 2 * DIM + d0 + tx];
    __syncthreads();
#pragma unroll
    for (int j = 0; j < 32; j += 8)
        vt[(size_t)b * DIM * SEQ + (size_t)(d0 + ty + j) * SEQ + n0 + tx] = t[tx][ty + j];
}

// ---------------- host-side tensormap setup --------------------------------
typedef CUresult (*PFN_encodeTiled)(
    CUtensorMap*, CUtensorMapDataType, cuuint32_t, void*,
    const cuuint64_t*, const cuuint64_t*, const cuuint32_t*, const cuuint32_t*,
    CUtensorMapInterleave, CUtensorMapSwizzle, CUtensorMapL2promotion,
    CUtensorMapFloatOOBfill);

static void make_map(PFN_encodeTiled enc, CUtensorMap* m, void* p,
                     uint64_t inner, uint64_t rows, uint64_t batch)
{
    cuuint64_t dims[3]    = {inner, rows, batch};
    cuuint64_t strides[2] = {inner * 2, inner * rows * 2};
    cuuint32_t box[3]     = {64, 128, 1};
    cuuint32_t es[3]      = {1, 1, 1};
    enc(m, CU_TENSOR_MAP_DATA_TYPE_FLOAT16, 3, p, dims, strides, box, es,
        CU_TENSOR_MAP_INTERLEAVE_NONE, CU_TENSOR_MAP_SWIZZLE_128B,
        CU_TENSOR_MAP_L2_PROMOTION_L2_128B, CU_TENSOR_MAP_FLOAT_OOB_FILL_NONE);
}

// ---------------------------------------------------------------------------
extern "C" void kernel_launch(void* const* d_in, const int* in_sizes, int n_in,
                              void* d_out, int out_size)
{
    const float* x      = (const float*)d_in[0];
    const float* w_qkv  = (const float*)d_in[1];
    const float* b_qkv  = (const float*)d_in[2];
    const float* w_proj = (const float*)d_in[3];
    const float* b_proj = (const float*)d_in[4];
    float* out = (float*)d_out;

    static __half *xh = nullptr, *wqkvh = nullptr, *wprojh = nullptr;
    static __half *qkvh = nullptr, *eh = nullptr, *vth = nullptr, *aoh = nullptr;
    static float *sums = nullptr;
    static CUtensorMap mXh, mWqkv, mQkv, mE, mVt, mAo, mWproj;
    if (!xh) {
        cudaGetSymbolAddress((void**)&xh,     g_xh);
        cudaGetSymbolAddress((void**)&wqkvh,  g_wqkvh);
        cudaGetSymbolAddress((void**)&wprojh, g_wprojh);
        cudaGetSymbolAddress((void**)&qkvh,   g_qkvh);
        cudaGetSymbolAddress((void**)&eh,     g_e);
        cudaGetSymbolAddress((void**)&sums,   g_sum);
        cudaGetSymbolAddress((void**)&vth,    g_vth);
        cudaGetSymbolAddress((void**)&aoh,    g_aoh);
        cudaFuncSetAttribute(gemm_tma<0>, cudaFuncAttributeMaxDynamicSharedMemorySize, SMEM_DYN);
        cudaFuncSetAttribute(gemm_tma<1>, cudaFuncAttributeMaxDynamicSharedMemorySize, SMEM_DYN);
        cudaFuncSetAttribute(gemm_tma<2>, cudaFuncAttributeMaxDynamicSharedMemorySize, SMEM_DYN);
        cudaFuncSetAttribute(gemm_tma<3>, cudaFuncAttributeMaxDynamicSharedMemorySize, SMEM_DYN);

        void* fn = nullptr;
        cudaDriverEntryPointQueryResult qr;
        cudaGetDriverEntryPoint("cuTensorMapEncodeTiled", &fn,
                                cudaEnableDefault, &qr);
        PFN_encodeTiled enc = (PFN_encodeTiled)fn;
        make_map(enc, &mXh,    xh,     DIM,  (uint64_t)BATCH * SEQ, 1);
        make_map(enc, &mWqkv,  wqkvh,  DIM,  QKVD,                  1);
        make_map(enc, &mQkv,   qkvh,   QKVD, SEQ,                   BATCH);
        make_map(enc, &mE,     eh,     SEQ,  SEQ,                   BATCH);
        make_map(enc, &mVt,    vth,    SEQ,  DIM,                   BATCH);
        make_map(enc, &mAo,    aoh,    DIM,  (uint64_t)BATCH * SEQ, 1);
        make_map(enc, &mWproj, wprojh, DIM,  DIM,                   1);
    }

    const int M_ALL = BATCH * SEQ;
    const float alpha_s = 1.0f / (sqrtf((float)DIM) * 3.0f);

    // 0) convert operands to fp16; zero rowsums
    {
        int n4 = BATCH * SEQ * DIM / 4;
        cvt_half_kernel<<<(n4 + 255) / 256, 256>>>((const float4*)x, (__half2*)xh, n4);
        n4 = QKVD * DIM / 4;
        cvt_half_kernel<<<(n4 + 255) / 256, 256>>>((const float4*)w_qkv, (__half2*)wqkvh, n4);
        n4 = DIM * DIM / 4;
        cvt_half_kernel<<<(n4 + 255) / 256, 256>>>((const float4*)w_proj, (__half2*)wprojh, n4);
        cudaMemsetAsync(sums, 0, (size_t)BATCH * SEQ * sizeof(float));
    }

    // 1) qkv = x @ w_qkv^T + b_qkv -> fp16
    gemm_tma<0><<<dim3(QKVD / BN, M_ALL / BM, 1), 256, SMEM_DYN>>>(
        mXh, mWqkv, 0, 0, b_qkv, nullptr, qkvh, DIM, QKVD, 0, 0, 1.0f);

    // 1b) Vt[b,d,n] fp16
    transpose_v<<<dim3(SEQ / 32, DIM / 32, BATCH), dim3(32, 8)>>>(qkvh, vth);

    // 2) E[b] = exp(alpha * Q_b @ K_b^T) -> fp16, + atomic rowsums
    gemm_tma<1><<<dim3(SEQ / BN, SEQ / BM, BATCH), 256, SMEM_DYN>>>(
        mQkv, mQkv, 0, DIM, nullptr, sums, eh,
        DIM, SEQ, (size_t)SEQ * SEQ, 0, alpha_s);

    // 3) attn_out[b] = (E_b @ Vt_b^T) / sums[row] -> fp16
    gemm_tma<2><<<dim3(DIM / BN, SEQ / BM, BATCH), 256, SMEM_DYN>>>(
        mE, mVt, 0, 0, sums, nullptr, aoh,
        SEQ, DIM, (size_t)SEQ * DIM, SEQ, 1.0f);

    // 4) out = attn_out @ w_proj^T + b_proj -> fp32
    gemm_tma<3><<<dim3(DIM / BN, M_ALL / BM, 1), 256, SMEM_DYN>>>(
        mAo, mWproj, 0, 0, b_proj, nullptr, out, DIM, DIM, 0, 0, 1.0f);
}

// round 15
// speedup vs baseline: 1.0433x; 1.0011x over previous
#include <cuda_runtime.h>
#include <cuda.h>
#include <cuda_fp16.h>
#include <cstdint>
#include <cstddef>
#include <math.h>

#define DIM   768
#define BATCH 8
#define SEQ   2048
#define QKVD  (3 * DIM)

// ------- scratch (static device globals; 1024B-aligned for TMA) -------------
__device__ __align__(1024) __half g_xh[(size_t)BATCH * SEQ * DIM];
__device__ __align__(1024) __half g_wqkvh[(size_t)QKVD * DIM];
__device__ __align__(1024) __half g_wprojh[(size_t)DIM * DIM];
__device__ __align__(1024) __half g_qkvh[(size_t)BATCH * SEQ * QKVD];
__device__ __align__(1024) __half g_e[(size_t)BATCH * SEQ * SEQ];
__device__ __align__(1024) float  g_sum[(size_t)BATCH * SEQ];
__device__ __align__(1024) __half g_vth[(size_t)BATCH * DIM * SEQ];
__device__ __align__(1024) __half g_aoh[(size_t)BATCH * SEQ * DIM];

// ---------------- PTX helpers ----------------------------------------------
__device__ __forceinline__ uint32_t smem_u32(const void* p) {
    uint32_t a;
    asm("{ .reg .u64 t; cvta.to.shared.u64 t, %1; cvt.u32.u64 %0, t; }"
        : "=r"(a) : "l"(p));
    return a;
}
__device__ __forceinline__ void mma_f16(float* d, const uint32_t* a, const uint32_t* b) {
    asm volatile(
        "mma.sync.aligned.m16n8k16.row.col.f32.f16.f16.f32 "
        "{%0,%1,%2,%3}, {%4,%5,%6,%7}, {%8,%9}, {%0,%1,%2,%3};"
        : "+f"(d[0]), "+f"(d[1]), "+f"(d[2]), "+f"(d[3])
        : "r"(a[0]), "r"(a[1]), "r"(a[2]), "r"(a[3]), "r"(b[0]), "r"(b[1]));
}
__device__ __forceinline__ void ldsm_x4(uint32_t& r0, uint32_t& r1,
                                        uint32_t& r2, uint32_t& r3, uint32_t addr) {
    asm volatile("ldmatrix.sync.aligned.m8n8.x4.shared.b16 {%0,%1,%2,%3}, [%4];"
                 : "=r"(r0), "=r"(r1), "=r"(r2), "=r"(r3) : "r"(addr));
}
__device__ __forceinline__ void mbar_init(uint32_t mbar, uint32_t cnt) {
    asm volatile("mbarrier.init.shared.b64 [%0], %1;" :: "r"(mbar), "r"(cnt) : "memory");
}
__device__ __forceinline__ void mbar_expect_tx(uint32_t mbar, uint32_t bytes) {
    asm volatile("mbarrier.arrive.expect_tx.shared.b64 _, [%0], %1;"
                 :: "r"(mbar), "r"(bytes) : "memory");
}
__device__ __forceinline__ void mbar_arrive(uint32_t mbar) {
    asm volatile("mbarrier.arrive.shared.b64 _, [%0];" :: "r"(mbar) : "memory");
}
__device__ __forceinline__ void mbar_wait(uint32_t mbar, uint32_t parity) {
    asm volatile(
        "{\n\t.reg .pred P;\n\t"
        "WLP_%=:\n\t"
        "mbarrier.try_wait.parity.acquire.cta.shared::cta.b64 P, [%0], %1, 0x989680;\n\t"
        "@P bra.uni WDN_%=;\n\t"
        "bra.uni WLP_%=;\n\t"
        "WDN_%=:\n\t}"
        :: "r"(mbar), "r"(parity) : "memory");
}
__device__ __forceinline__ void tma_load3d(uint32_t dst, const CUtensorMap* map,
                                           int x, int y, int z, uint32_t mbar) {
    asm volatile(
        "cp.async.bulk.tensor.3d.shared::cta.global.tile.mbarrier::complete_tx::bytes "
        "[%0], [%1, {%2, %3, %4}], [%5];"
        :: "r"(dst), "l"(map), "r"(x), "r"(y), "r"(z), "r"(mbar) : "memory");
}

// ---------------- GEMM config ----------------------------------------------
// C[M,N] = f(alpha * A[M,K] @ B[N,K]^T). fp16 via TMA, accum fp32.
// 128x128x64 tiles, 256 thr, 3-stage TMA+mbarrier ring, software-pipelined
// fragment loads (A ping-pong across k-steps, B pairs streamed), 2 CTAs/SM.
// MODE 0: +bias fp16 | 1: exp + rowsum fp16 | 2: /sums[row] fp16 | 3: +bias fp32
constexpr int BM = 128, BN = 128, BK = 64, NSTAGE = 3;
constexpr int TILE_BYTES  = BM * 128;                   // 16384
constexpr int STAGE_BYTES = 2 * TILE_BYTES;             // 32768
constexpr int SMEM_DYN    = NSTAGE * STAGE_BYTES + 1024;

template <int MODE>
__global__ __launch_bounds__(256, 2)
void gemm_tma(const __grid_constant__ CUtensorMap mapA,
              const __grid_constant__ CUtensorMap mapB,
              int kOffA, int kOffB,
              const float* __restrict__ aux, float* __restrict__ sums,
              void* __restrict__ Cv,
              int K, int ldc, size_t sC, size_t sAux, float alpha)
{
    extern __shared__ char smem_raw[];
    __shared__ __align__(8) uint64_t s_full[NSTAGE];
    __shared__ __align__(8) uint64_t s_empty[NSTAGE];
    const uint32_t smem0 = (smem_u32(smem_raw) + 1023u) & ~1023u;

    const int tid  = threadIdx.x;
    const int wid  = tid >> 5;
    const int lane = tid & 31;
    const int g    = lane >> 2;
    const int tig  = lane & 3;
    const int wm0  = (wid & 3) * 32;
    const int wn0  = (wid >> 2) * 64;

    const int brow = blockIdx.y * BM;
    const int bcol = blockIdx.x * BN;
    const int bz   = blockIdx.z;

    const int iters = K / BK;

    if (tid == 0) {
#pragma unroll
        for (int s = 0; s < NSTAGE; s++) {
            mbar_init(smem_u32(&s_full[s]), 1);
            mbar_init(smem_u32(&s_empty[s]), 8);   // one arrive per warp
        }
        asm volatile("fence.proxy.async.shared::cta;" ::: "memory");
    }
    __syncthreads();

    if (tid == 0) {
#pragma unroll
        for (int s = 0; s < NSTAGE; s++) {
            const uint32_t sa = smem0 + s * STAGE_BYTES;
            mbar_expect_tx(smem_u32(&s_full[s]), STAGE_BYTES);
            tma_load3d(sa, &mapA, s * BK + kOffA, brow, bz, smem_u32(&s_full[s]));
            tma_load3d(sa + TILE_BYTES, &mapB, s * BK + kOffB, bcol, bz,
                       smem_u32(&s_full[s]));
        }
    }

    const uint32_t hi = (uint32_t)(lane >> 4);
    uint32_t aoff[2], axr[2], boff[4], bxr[4];
#pragma unroll
    for (int mi = 0; mi < 2; mi++) {
        int row = wm0 + mi * 16 + (lane & 15);
        aoff[mi] = (uint32_t)(row * 128);
        axr[mi]  = (uint32_t)(row & 7);
    }
#pragma unroll
    for (int p = 0; p < 4; p++) {
        int row = wn0 + p * 16 + (lane & 15);
        boff[p] = (uint32_t)(row * 128);
        bxr[p]  = (uint32_t)(row & 7);
    }

    float acc[2][8][4];
#pragma unroll
    for (int mi = 0; mi < 2; mi++)
#pragma unroll
        for (int ni = 0; ni < 8; ni++)
#pragma unroll
            for (int r = 0; r < 4; r++) acc[mi][ni][r] = 0.0f;

    // one tile of work on stage s (compile-time), parity u, iteration it
    auto body = [&](int s, uint32_t u, int it) {
        mbar_wait(smem_u32(&s_full[s]), u);
        const uint32_t sa = smem0 + s * STAGE_BYTES;
        const uint32_t sb = sa + TILE_BYTES;

        // A fragments for ks=0
        uint32_t afc[2][4];
#pragma unroll
        for (int mi = 0; mi < 2; mi++)
            ldsm_x4(afc[mi][0], afc[mi][1], afc[mi][2], afc[mi][3],
                    sa + aoff[mi] + ((hi ^ axr[mi]) << 4));

#pragma unroll
        for (int ks = 0; ks < 4; ks++) {
            const uint32_t ch = 2 * ks + hi;

            // prefetch A fragments for next k-step (hidden behind B-stream MMAs)
            uint32_t afn[2][4];
            if (ks < 3) {
                const uint32_t chn = 2 * (ks + 1) + hi;
#pragma unroll
                for (int mi = 0; mi < 2; mi++)
                    ldsm_x4(afn[mi][0], afn[mi][1], afn[mi][2], afn[mi][3],
                            sa + aoff[mi] + ((chn ^ axr[mi]) << 4));
            }

            // stream B pairs: load pair p+1 between the MMAs of pair p
            uint32_t c0[2], c1[2];
            ldsm_x4(c0[0], c1[0], c0[1], c1[1],
                    sb + boff[0] + ((ch ^ bxr[0]) << 4));
#pragma unroll
            for (int p = 0; p < 4; p++) {
                uint32_t n0[2], n1[2];
                if (p < 3)
                    ldsm_x4(n0[0], n1[0], n0[1], n1[1],
                            sb + boff[p + 1] + ((ch ^ bxr[p + 1]) << 4));
                mma_f16(acc[0][2 * p],     afc[0], c0);
                mma_f16(acc[0][2 * p + 1], afc[0], c1);
                mma_f16(acc[1][2 * p],     afc[1], c0);
                mma_f16(acc[1][2 * p + 1], afc[1], c1);
                if (p < 3) {
                    c0[0] = n0[0]; c0[1] = n0[1];
                    c1[0] = n1[0]; c1[1] = n1[1];
                }
            }

            if (ks < 3) {
#pragma unroll
                for (int mi = 0; mi < 2; mi++)
#pragma unroll
                    for (int r = 0; r < 4; r++) afc[mi][r] = afn[mi][r];
            }
        }

        if (lane == 0) mbar_arrive(smem_u32(&s_empty[s]));
        if (tid == 0 && it + NSTAGE < iters) {
            mbar_wait(smem_u32(&s_empty[s]), u);
            mbar_expect_tx(smem_u32(&s_full[s]), STAGE_BYTES);
            tma_load3d(sa, &mapA, (it + NSTAGE) * BK + kOffA, brow, bz,
                       smem_u32(&s_full[s]));
            tma_load3d(sb, &mapB, (it + NSTAGE) * BK + kOffB, bcol, bz,
                       smem_u32(&s_full[s]));
        }
    };

    const int nfull = iters / NSTAGE;
    const int nrem  = iters - nfull * NSTAGE;
    int it = 0;
    for (int blk = 0; blk < nfull; blk++) {
        const uint32_t u = (uint32_t)blk & 1u;
#pragma unroll
        for (int s = 0; s < NSTAGE; s++) { body(s, u, it); it++; }
    }
    {
        const uint32_t u = (uint32_t)nfull & 1u;
#pragma unroll
        for (int s = 0; s < NSTAGE - 1; s++) {
            if (s < nrem) { body(s, u, it); it++; }
        }
    }

    // ---- epilogue ----
    float2 bv[8];
    if (MODE == 0 || MODE == 3) {
#pragma unroll
        for (int ni = 0; ni < 8; ni++)
            bv[ni] = *reinterpret_cast<const float2*>(&aux[bcol + wn0 + ni * 8 + 2 * tig]);
    }
    float rs[2][2];
    if (MODE == 2) {
        const float* sm = aux + (size_t)bz * sAux;
#pragma unroll
        for (int mi = 0; mi < 2; mi++) {
            const int r0 = brow + wm0 + mi * 16 + g;
            rs[mi][0] = 1.0f / sm[r0];
            rs[mi][1] = 1.0f / sm[r0 + 8];
        }
    }
    float rowacc[2][2];
    if (MODE == 1) {
        rowacc[0][0] = rowacc[0][1] = rowacc[1][0] = rowacc[1][1] = 0.0f;
    }
#pragma unroll
    for (int mi = 0; mi < 2; mi++) {
        const int r0 = brow + wm0 + mi * 16 + g;
#pragma unroll
        for (int ni = 0; ni < 8; ni++) {
            const int c = bcol + wn0 + ni * 8 + 2 * tig;
            float2 v0, v1;
            v0.x = acc[mi][ni][0] * alpha;
            v0.y = acc[mi][ni][1] * alpha;
            v1.x = acc[mi][ni][2] * alpha;
            v1.y = acc[mi][ni][3] * alpha;
            if (MODE == 0 || MODE == 3) {
                v0.x += bv[ni].x; v0.y += bv[ni].y;
                v1.x += bv[ni].x; v1.y += bv[ni].y;
            }
            if (MODE == 1) {
                v0.x = __expf(v0.x); v0.y = __expf(v0.y);
                v1.x = __expf(v1.x); v1.y = __expf(v1.y);
                rowacc[mi][0] += v0.x + v0.y;
                rowacc[mi][1] += v1.x + v1.y;
            }
            if (MODE == 2) {
                v0.x *= rs[mi][0]; v0.y *= rs[mi][0];
                v1.x *= rs[mi][1]; v1.y *= rs[mi][1];
            }
            if (MODE == 3) {
                float* C = (float*)Cv + (size_t)bz * sC;
                *reinterpret_cast<float2*>(&C[(size_t)r0 * ldc + c]) = v0;
                *reinterpret_cast<float2*>(&C[(size_t)(r0 + 8) * ldc + c]) = v1;
            } else {
                __half* C = (__half*)Cv + (size_t)bz * sC;
                *reinterpret_cast<__half2*>(&C[(size_t)r0 * ldc + c]) =
                    __floats2half2_rn(v0.x, v0.y);
                *reinterpret_cast<__half2*>(&C[(size_t)(r0 + 8) * ldc + c]) =
                    __floats2half2_rn(v1.x, v1.y);
            }
        }
    }
    if (MODE == 1) {
#pragma unroll
        for (int mi = 0; mi < 2; mi++) {
#pragma unroll
            for (int h = 0; h < 2; h++) {
                float v = rowacc[mi][h];
                v += __shfl_xor_sync(0xffffffffu, v, 1);
                v += __shfl_xor_sync(0xffffffffu, v, 2);
                if (tig == 0) {
                    const int r0 = brow + wm0 + mi * 16 + g + h * 8;
                    atomicAdd(&sums[(size_t)bz * SEQ + r0], v);
                }
            }
        }
    }
}

// ---------------- fp32 -> fp16 conversion ----------------------------------
__global__ __launch_bounds__(256) void cvt_half_kernel(const float4* __restrict__ in,
                                                       __half2* __restrict__ out, int n4)
{
    int i = blockIdx.x * blockDim.x + threadIdx.x;
    if (i < n4) {
        float4 v = in[i];
        out[2 * i]     = __floats2half2_rn(v.x, v.y);
        out[2 * i + 1] = __floats2half2_rn(v.z, v.w);
    }
}

// ---------------- V transpose: qkvh[b,n,2*DIM+d] -> vth[b,d,n] -------------
__global__ __launch_bounds__(256) void transpose_v(const __half* __restrict__ qkv,
                                                   __half* __restrict__ vt)
{
    __shared__ __half t[32][34];
    const int b = blockIdx.z;
    const int n0 = blockIdx.x * 32, d0 = blockIdx.y * 32;
    const int tx = threadIdx.x, ty = threadIdx.y;   // 32 x 8
#pragma unroll
    for (int j = 0; j < 32; j += 8)
        t[ty + j][tx] = qkv[(size_t)b * SEQ * QKVD + (size_t)(n0 + ty + j) * QKVD
                            + 2 * DIM + d0 + tx];
    __syncthreads();
#pragma unroll
    for (int j = 0; j < 32; j += 8)
        vt[(size_t)b * DIM * SEQ + (size_t)(d0 + ty + j) * SEQ + n0 + tx] = t[tx][ty + j];
}

// ---------------- host-side tensormap setup --------------------------------
typedef CUresult (*PFN_encodeTiled)(
    CUtensorMap*, CUtensorMapDataType, cuuint32_t, void*,
    const cuuint64_t*, const cuuint64_t*, const cuuint32_t*, const cuuint32_t*,
    CUtensorMapInterleave, CUtensorMapSwizzle, CUtensorMapL2promotion,
    CUtensorMapFloatOOBfill);

static void make_map(PFN_encodeTiled enc, CUtensorMap* m, void* p,
                     uint64_t inner, uint64_t rows, uint64_t batch)
{
    cuuint64_t dims[3]    = {inner, rows, batch};
    cuuint64_t strides[2] = {inner * 2, inner * rows * 2};
    cuuint32_t box[3]     = {64, 128, 1};
    cuuint32_t es[3]      = {1, 1, 1};
    enc(m, CU_TENSOR_MAP_DATA_TYPE_FLOAT16, 3, p, dims, strides, box, es,
        CU_TENSOR_MAP_INTERLEAVE_NONE, CU_TENSOR_MAP_SWIZZLE_128B,
        CU_TENSOR_MAP_L2_PROMOTION_L2_128B, CU_TENSOR_MAP_FLOAT_OOB_FILL_NONE);
}

// ---------------------------------------------------------------------------
extern "C" void kernel_launch(void* const* d_in, const int* in_sizes, int n_in,
                              void* d_out, int out_size)
{
    const float* x      = (const float*)d_in[0];
    const float* w_qkv  = (const float*)d_in[1];
    const float* b_qkv  = (const float*)d_in[2];
    const float* w_proj = (const float*)d_in[3];
    const float* b_proj = (const float*)d_in[4];
    float* out = (float*)d_out;

    static __half *xh = nullptr, *wqkvh = nullptr, *wprojh = nullptr;
    static __half *qkvh = nullptr, *eh = nullptr, *vth = nullptr, *aoh = nullptr;
    static float *sums = nullptr;
    static CUtensorMap mXh, mWqkv, mQkv, mE, mVt, mAo, mWproj;
    if (!xh) {
        cudaGetSymbolAddress((void**)&xh,     g_xh);
        cudaGetSymbolAddress((void**)&wqkvh,  g_wqkvh);
        cudaGetSymbolAddress((void**)&wprojh, g_wprojh);
        cudaGetSymbolAddress((void**)&qkvh,   g_qkvh);
        cudaGetSymbolAddress((void**)&eh,     g_e);
        cudaGetSymbolAddress((void**)&sums,   g_sum);
        cudaGetSymbolAddress((void**)&vth,    g_vth);
        cudaGetSymbolAddress((void**)&aoh,    g_aoh);
        cudaFuncSetAttribute(gemm_tma<0>, cudaFuncAttributeMaxDynamicSharedMemorySize, SMEM_DYN);
        cudaFuncSetAttribute(gemm_tma<1>, cudaFuncAttributeMaxDynamicSharedMemorySize, SMEM_DYN);
        cudaFuncSetAttribute(gemm_tma<2>, cudaFuncAttributeMaxDynamicSharedMemorySize, SMEM_DYN);
        cudaFuncSetAttribute(gemm_tma<3>, cudaFuncAttributeMaxDynamicSharedMemorySize, SMEM_DYN);

        void* fn = nullptr;
        cudaDriverEntryPointQueryResult qr;
        cudaGetDriverEntryPoint("cuTensorMapEncodeTiled", &fn,
                                cudaEnableDefault, &qr);
        PFN_encodeTiled enc = (PFN_encodeTiled)fn;
        make_map(enc, &mXh,    xh,     DIM,  (uint64_t)BATCH * SEQ, 1);
        make_map(enc, &mWqkv,  wqkvh,  DIM,  QKVD,                  1);
        make_map(enc, &mQkv,   qkvh,   QKVD, SEQ,                   BATCH);
        make_map(enc, &mE,     eh,     SEQ,  SEQ,                   BATCH);
        make_map(enc, &mVt,    vth,    SEQ,  DIM,                   BATCH);
        make_map(enc, &mAo,    aoh,    DIM,  (uint64_t)BATCH * SEQ, 1);
        make_map(enc, &mWproj, wprojh, DIM,  DIM,                   1);
    }

    const int M_ALL = BATCH * SEQ;
    const float alpha_s = 1.0f / (sqrtf((float)DIM) * 3.0f);

    // 0) convert operands to fp16; zero rowsums
    {
        int n4 = BATCH * SEQ * DIM / 4;
        cvt_half_kernel<<<(n4 + 255) / 256, 256>>>((const float4*)x, (__half2*)xh, n4);
        n4 = QKVD * DIM / 4;
        cvt_half_kernel<<<(n4 + 255) / 256, 256>>>((const float4*)w_qkv, (__half2*)wqkvh, n4);
        n4 = DIM * DIM / 4;
        cvt_half_kernel<<<(n4 + 255) / 256, 256>>>((const float4*)w_proj, (__half2*)wprojh, n4);
        cudaMemsetAsync(sums, 0, (size_t)BATCH * SEQ * sizeof(float));
    }

    // 1) qkv = x @ w_qkv^T + b_qkv -> fp16
    gemm_tma<0><<<dim3(QKVD / BN, M_ALL / BM, 1), 256, SMEM_DYN>>>(
        mXh, mWqkv, 0, 0, b_qkv, nullptr, qkvh, DIM, QKVD, 0, 0, 1.0f);

    // 1b) Vt[b,d,n] fp16
    transpose_v<<<dim3(SEQ / 32, DIM / 32, BATCH), dim3(32, 8)>>>(qkvh, vth);

    // 2) E[b] = exp(alpha * Q_b @ K_b^T) -> fp16, + atomic rowsums
    gemm_tma<1><<<dim3(SEQ / BN, SEQ / BM, BATCH), 256, SMEM_DYN>>>(
        mQkv, mQkv, 0, DIM, nullptr, sums, eh,
        DIM, SEQ, (size_t)SEQ * SEQ, 0, alpha_s);

    // 3) attn_out[b] = (E_b @ Vt_b^T) / sums[row] -> fp16
    gemm_tma<2><<<dim3(DIM / BN, SEQ / BM, BATCH), 256, SMEM_DYN>>>(
        mE, mVt, 0, 0, sums, nullptr, aoh,
        SEQ, DIM, (size_t)SEQ * DIM, SEQ, 1.0f);

    // 4) out = attn_out @ w_proj^T + b_proj -> fp32
    gemm_tma<3><<<dim3(DIM / BN, M_ALL / BM, 1), 256, SMEM_DYN>>>(
        mAo, mWproj, 0, 0, b_proj, nullptr, out, DIM, DIM, 0, 0, 1.0f);
}